// round 16
// baseline (speedup 1.0000x reference)
#include <cuda_runtime.h>
#include <math.h>
#include <stdint.h>

#define Bb      2
#define Ll      4096
#define DMODEL  1024
#define DINNER  2048
#define NHEADS  32
#define HEADDIM 64
#define DSTATE  128
#define DIP     4384
#define CONVDIM 2304
#define BL      (Bb*Ll)
#define DOUT    1024
#define Q       32
#define NC      (Ll/Q)
#define SSTATE  (HEADDIM*DSTATE)
#define BSTR    132
#define XSTR    36

__device__ float g_zx    [(size_t)BL * DIP];
__device__ float g_xbc   [(size_t)BL * CONVDIM];
__device__ float g_y     [(size_t)BL * DINNER];
__device__ float g_dt    [BL * NHEADS];
__device__ float g_dA    [BL * NHEADS];
__device__ float g_xc    [(size_t)BL * DMODEL];
__device__ float g_w1    [(size_t)DIP * DMODEL];
__device__ float g_w2    [(size_t)DOUT * DINNER];
__device__ float g_state [(size_t)Bb*NHEADS * NC * SSTATE];
__device__ float g_sprev [(size_t)Bb*NHEADS * NC * SSTATE];
__device__ float g_ca    [(size_t)Bb*NHEADS * NC * Q];
__device__ float g_bcs_hi[(size_t)BL * 256];
__device__ float g_bcs_lo[(size_t)BL * 256];

__device__ __forceinline__ uint32_t f2tf(float f) {
    uint32_t r; asm("cvt.rna.tf32.f32 %0, %1;" : "=r"(r) : "f"(f)); return r;
}
__device__ __forceinline__ void split_store(float v, float* hi, float* lo) {
    float h = __uint_as_float(f2tf(v));
    *hi = h; *lo = __uint_as_float(f2tf(v - h));
}
__device__ __forceinline__ void mma_tf32(float c[4], const uint32_t a[4], const uint32_t b[2]) {
    asm volatile(
        "mma.sync.aligned.m16n8k8.row.col.f32.tf32.tf32.f32 "
        "{%0,%1,%2,%3}, {%4,%5,%6,%7}, {%8,%9}, {%0,%1,%2,%3};"
        : "+f"(c[0]), "+f"(c[1]), "+f"(c[2]), "+f"(c[3])
        : "r"(a[0]), "r"(a[1]), "r"(a[2]), "r"(a[3]), "r"(b[0]), "r"(b[1]));
}
__device__ __forceinline__ void mma_split(float c[4], const uint32_t ah[4], const uint32_t al[4],
                                          const uint32_t bh[2], const uint32_t bl[2]) {
    mma_tf32(c, ah, bh); mma_tf32(c, ah, bl); mma_tf32(c, al, bh);
}
__device__ __forceinline__ void ldsm_x4(uint32_t& r0, uint32_t& r1, uint32_t& r2, uint32_t& r3,
                                        uint32_t addr) {
    asm volatile("ldmatrix.sync.aligned.m8n8.x4.shared.b16 {%0,%1,%2,%3}, [%4];"
                 : "=r"(r0), "=r"(r1), "=r"(r2), "=r"(r3) : "r"(addr));
}
__device__ __forceinline__ uint32_t smem_u32(const void* p) {
    return (uint32_t)__cvta_generic_to_shared(p);
}

__global__ __launch_bounds__(256) void cvt_tf32_kernel(
    const float* __restrict__ src, float* __restrict__ dst, int n4)
{
    const int i = blockIdx.x * blockDim.x + threadIdx.x;
    if (i >= n4) return;
    float4 v = ((const float4*)src)[i];
    uint4 u;
    u.x = f2tf(v.x); u.y = f2tf(v.y); u.z = f2tf(v.z); u.w = f2tf(v.w);
    ((uint4*)dst)[i] = u;
}

// ============== TF32 GEMM (NT): 3-stage cp.async, SW128 smem, LDSM (R15) ==============
#define TSTAGE_F 4096
#define TSTAGE_B (2 * TSTAGE_F * 4)

__global__ __launch_bounds__(256, 2) void gemm_tf32_ca_kernel(
    const float* __restrict__ A, const float* __restrict__ Bw,
    float* __restrict__ C, int M, int N, int K)
{
    extern __shared__ float sm[];

    const int tid  = threadIdx.x;
    const int lane = tid & 31;
    const int warp = tid >> 5;
    const int wm = (warp >> 2) * 64;
    const int wn = (warp & 3) * 32;
    const int bm = blockIdx.y * 128;
    const int bn = blockIdx.x * 128;

    const int r    = tid >> 1;
    const int ccol = (tid & 1) * 16;
    uint32_t doff[4];
#pragma unroll
    for (int j = 0; j < 4; j++) {
        const uint32_t lc = (uint32_t)((tid & 1) * 4 + j);
        doff[j] = (uint32_t)r * 128u + ((lc ^ ((uint32_t)r & 7u)) * 16u);
    }
    const float* Ag = A  + (size_t)(bm + r) * K + ccol;
    const float* Bg = Bw + (size_t)(bn + r) * K + ccol;
    const int bsz = ((bn + r) < N) ? 16 : 0;
    const uint32_t sbase = smem_u32(sm);

#define G_ISSUE(kt, s) do {                                                    \
        const float* ag_ = Ag + (size_t)(kt) * 32;                             \
        const float* bg_ = Bg + (size_t)(kt) * 32;                             \
        const uint32_t da_ = sbase + (uint32_t)(s) * TSTAGE_B;                 \
        const uint32_t db_ = da_ + TSTAGE_F * 4;                               \
        _Pragma("unroll")                                                      \
        for (int j_ = 0; j_ < 4; j_++)                                         \
            asm volatile("cp.async.cg.shared.global [%0], [%1], 16;"           \
                         :: "r"(da_ + doff[j_]), "l"(ag_ + j_ * 4));           \
        _Pragma("unroll")                                                      \
        for (int j_ = 0; j_ < 4; j_++)                                         \
            asm volatile("cp.async.cg.shared.global [%0], [%1], 16, %2;"       \
                         :: "r"(db_ + doff[j_]), "l"(bg_ + j_ * 4), "r"(bsz)); \
        asm volatile("cp.async.commit_group;");                                \
    } while (0)

    float acc[4][4][4];
#pragma unroll
    for (int mt = 0; mt < 4; mt++)
#pragma unroll
        for (int nt = 0; nt < 4; nt++)
#pragma unroll
            for (int i = 0; i < 4; i++) acc[mt][nt][i] = 0.f;

    const uint32_t x7   = (uint32_t)(lane & 7);
    const uint32_t aRow = x7 + (uint32_t)((lane >> 3) & 1) * 8u;
    const uint32_t aE   = (uint32_t)(lane >> 4);
    const uint32_t bRow = x7 + (uint32_t)(lane >> 4) * 8u;
    const uint32_t bE   = (uint32_t)((lane >> 3) & 1);

    const int KT = K / 32;

    G_ISSUE(0, 0);
    G_ISSUE(1, 1);

    for (int kt = 0; kt < KT; kt++) {
        if (kt + 1 < KT) asm volatile("cp.async.wait_group 1;");
        else             asm volatile("cp.async.wait_group 0;");
        __syncthreads();
        if (kt + 2 < KT) G_ISSUE(kt + 2, (kt + 2) % 3);

        const uint32_t aStage = sbase + (uint32_t)(kt % 3) * TSTAGE_B;
        const uint32_t bStage = aStage + TSTAGE_F * 4;
        uint32_t aBase[4], bBase[2];
#pragma unroll
        for (int mt = 0; mt < 4; mt++)
            aBase[mt] = aStage + (uint32_t)(wm + mt * 16 + aRow) * 128u;
#pragma unroll
        for (int np = 0; np < 2; np++)
            bBase[np] = bStage + (uint32_t)(wn + np * 16 + bRow) * 128u;

#pragma unroll
        for (int ks = 0; ks < 4; ks++) {
            const uint32_t ka = (((uint32_t)(2 * ks) + aE) ^ x7) * 16u;
            const uint32_t kb = (((uint32_t)(2 * ks) + bE) ^ x7) * 16u;
            uint32_t af[4][4];
#pragma unroll
            for (int mt = 0; mt < 4; mt++)
                ldsm_x4(af[mt][0], af[mt][1], af[mt][2], af[mt][3], aBase[mt] + ka);
            uint32_t bf[4][2];
#pragma unroll
            for (int np = 0; np < 2; np++)
                ldsm_x4(bf[2*np][0], bf[2*np][1], bf[2*np+1][0], bf[2*np+1][1],
                        bBase[np] + kb);
#pragma unroll
            for (int mt = 0; mt < 4; mt++)
#pragma unroll
                for (int nt = 0; nt < 4; nt++)
                    mma_tf32(acc[mt][nt], af[mt], bf[nt]);
        }
    }

#pragma unroll
    for (int mt = 0; mt < 4; mt++) {
        const int row = bm + wm + mt * 16 + (lane >> 2);
#pragma unroll
        for (int nt = 0; nt < 4; nt++) {
            const int col = bn + wn + nt * 8 + (lane & 3) * 2;
            if (col < N) {
                *(float2*)&C[(size_t)row * N + col]       = make_float2(acc[mt][nt][0], acc[mt][nt][1]);
                *(float2*)&C[(size_t)(row + 8) * N + col] = make_float2(acc[mt][nt][2], acc[mt][nt][3]);
            }
        }
    }
#undef G_ISSUE
}

// ============== depthwise conv + SiLU + pre-split B/C ==============
__global__ __launch_bounds__(256) void conv_silu_kernel(
    const float* __restrict__ conv_w, const float* __restrict__ conv_b)
{
    const int idx = blockIdx.x * blockDim.x + threadIdx.x;
    if (idx >= BL * (CONVDIM / 4)) return;
    const int c4 = (idx % (CONVDIM / 4)) * 4;
    const int bl = idx / (CONVDIM / 4);
    const int l  = bl & (Ll - 1);

    float4 acc = *(const float4*)(conv_b + c4);
    float4 w0 = *(const float4*)(conv_w + (c4 + 0) * 4);
    float4 w1 = *(const float4*)(conv_w + (c4 + 1) * 4);
    float4 w2 = *(const float4*)(conv_w + (c4 + 2) * 4);
    float4 w3 = *(const float4*)(conv_w + (c4 + 3) * 4);

    const float* col = g_zx + (size_t)bl * DIP + DINNER + c4;
#pragma unroll
    for (int j = 0; j < 4; j++) {
        const int ls = l - 3 + j;
        if (ls >= 0) {
            float4 v = *(const float4*)(col + (long)(j - 3) * DIP);
            acc.x = fmaf(v.x, (&w0.x)[j], acc.x);
            acc.y = fmaf(v.y, (&w1.x)[j], acc.y);
            acc.z = fmaf(v.z, (&w2.x)[j], acc.z);
            acc.w = fmaf(v.w, (&w3.x)[j], acc.w);
        }
    }
    float4 o;
    o.x = acc.x / (1.f + expf(-acc.x));
    o.y = acc.y / (1.f + expf(-acc.y));
    o.z = acc.z / (1.f + expf(-acc.z));
    o.w = acc.w / (1.f + expf(-acc.w));

    if (c4 < DINNER) {
        *(float4*)(g_xbc + (size_t)bl * CONVDIM + c4) = o;
    } else {
        const int q = c4 - DINNER;
        float4 h4, l4;
        h4.x = __uint_as_float(f2tf(o.x)); l4.x = __uint_as_float(f2tf(o.x - h4.x));
        h4.y = __uint_as_float(f2tf(o.y)); l4.y = __uint_as_float(f2tf(o.y - h4.y));
        h4.z = __uint_as_float(f2tf(o.z)); l4.z = __uint_as_float(f2tf(o.z - h4.z));
        h4.w = __uint_as_float(f2tf(o.w)); l4.w = __uint_as_float(f2tf(o.w - h4.w));
        *(float4*)(g_bcs_hi + (size_t)bl * 256 + q) = h4;
        *(float4*)(g_bcs_lo + (size_t)bl * 256 + q) = l4;
    }
}

// ============== dt: softplus; a = dt * (-exp(A_log)) ==============
__global__ __launch_bounds__(256) void dt_kernel(
    const float* __restrict__ dt_bias, const float* __restrict__ A_log)
{
    const int idx = blockIdx.x * blockDim.x + threadIdx.x;
    if (idx >= BL * NHEADS) return;
    const int h  = idx & (NHEADS - 1);
    const int bl = idx >> 5;
    float raw = g_zx[(size_t)bl * DIP + DINNER + CONVDIM + h] + dt_bias[h];
    float dt = (raw > 20.f) ? raw : log1pf(expf(raw));
    float A = -expf(A_log[h]);
    g_dt[idx] = dt;
    g_dA[idx] = dt * A;
}

// ============== SSD K1 (LDSM fragments) ==============
__global__ __launch_bounds__(256, 2) void ssd_chunk_kernel()
{
    extern __shared__ float smf[];
    float* sBhi = smf;
    float* sBlo = sBhi + Q * BSTR;
    float* sWhi = sBlo + Q * BSTR;   // C during G; Xw ([64][XSTR]) after
    float* sWlo = sWhi + Q * BSTR;
    float* sXhi = sWlo + Q * BSTR;   // Xt [64][XSTR]
    float* sXlo = sXhi + 64 * XSTR;
    float* sMhi = sXlo + 64 * XSTR;  // [Q][XSTR]
    float* sMlo = sMhi + Q * XSTR;
    float* s_dt = sMlo + Q * XSTR;
    float* s_ca = s_dt + Q;
    float* s_w  = s_ca + Q;

    const int tid  = threadIdx.x;
    const int lane = tid & 31;
    const int warp = tid >> 5;
    const int bx = blockIdx.x;
    const int h = bx & 31;
    const int c = (bx >> 5) & (NC - 1);
    const int b = bx >> 12;
    const int t0 = c * Q;
    const int bh = b * NHEADS + h;
    const float* xbase = g_xbc + ((size_t)b * Ll + t0) * CONVDIM;

    {
        const int t  = tid >> 3;
        const int l8 = (tid & 7) * 16;
        const size_t row = (size_t)(b * Ll + t0 + t) * 256;
        const float* hs = g_bcs_hi + row;
        const float* ls = g_bcs_lo + row;
        const uint32_t base = smem_u32(smf);
        const uint32_t off = (uint32_t)(t * BSTR + l8) * 4u;
        const uint32_t dB_hi = base + off;
        const uint32_t dB_lo = dB_hi + Q * BSTR * 4u;
        const uint32_t dW_hi = dB_lo + Q * BSTR * 4u;
        const uint32_t dW_lo = dW_hi + Q * BSTR * 4u;
#pragma unroll
        for (int j = 0; j < 4; j++) {
            asm volatile("cp.async.cg.shared.global [%0], [%1], 16;"
                         :: "r"(dB_hi + j * 16), "l"(hs + l8 + j * 4));
            asm volatile("cp.async.cg.shared.global [%0], [%1], 16;"
                         :: "r"(dB_lo + j * 16), "l"(ls + l8 + j * 4));
            asm volatile("cp.async.cg.shared.global [%0], [%1], 16;"
                         :: "r"(dW_hi + j * 16), "l"(hs + 128 + l8 + j * 4));
            asm volatile("cp.async.cg.shared.global [%0], [%1], 16;"
                         :: "r"(dW_lo + j * 16), "l"(ls + 128 + l8 + j * 4));
        }
        asm volatile("cp.async.commit_group;");
    }
    {
        const int t  = tid & 31;
        const int p0 = (tid >> 5) * 8;
        const float4* srcX = (const float4*)(xbase + (size_t)t * CONVDIM + h * 64 + p0);
        float4 v0 = srcX[0];
        float4 v1 = srcX[1];
        split_store(v0.x, &sXhi[(p0+0)*XSTR+t], &sXlo[(p0+0)*XSTR+t]);
        split_store(v0.y, &sXhi[(p0+1)*XSTR+t], &sXlo[(p0+1)*XSTR+t]);
        split_store(v0.z, &sXhi[(p0+2)*XSTR+t], &sXlo[(p0+2)*XSTR+t]);
        split_store(v0.w, &sXhi[(p0+3)*XSTR+t], &sXlo[(p0+3)*XSTR+t]);
        split_store(v1.x, &sXhi[(p0+4)*XSTR+t], &sXlo[(p0+4)*XSTR+t]);
        split_store(v1.y, &sXhi[(p0+5)*XSTR+t], &sXlo[(p0+5)*XSTR+t]);
        split_store(v1.z, &sXhi[(p0+6)*XSTR+t], &sXlo[(p0+6)*XSTR+t]);
        split_store(v1.w, &sXhi[(p0+7)*XSTR+t], &sXlo[(p0+7)*XSTR+t]);
    }
    if (tid < 32) {
        const size_t rb = ((size_t)b * Ll + t0 + tid) * NHEADS + h;
        const float dtv = g_dt[rb];
        float cum = g_dA[rb];
        s_dt[tid] = dtv;
#pragma unroll
        for (int o = 1; o < 32; o <<= 1) {
            float nb = __shfl_up_sync(0xffffffffu, cum, o);
            if (tid >= o) cum += nb;
        }
        s_ca[tid] = cum;
        g_ca[((size_t)bh * NC + c) * Q + tid] = cum;
        const float tot = __shfl_sync(0xffffffffu, cum, 31);
        s_w[tid] = dtv * expf(tot - cum);
    }
    asm volatile("cp.async.wait_group 0;");
    __syncthreads();

    // ---- common LDSM lane indices ----
    const uint32_t l7 = (uint32_t)(lane & 7);
    const uint32_t jt = (uint32_t)(lane >> 3);      // tile index 0..3

    // ---- G = C @ B^T (32x32x128), LDSM fragments, dual acc ----
    const int wmG = (warp >> 2) * 16;
    const int wnG = (warp & 3) * 8;
    float gaccA[4] = {0.f, 0.f, 0.f, 0.f};
    float gaccB[4] = {0.f, 0.f, 0.f, 0.f};
    {
        // A (C tile): row = wmG + (jt&1)*8 + l7, colofs = (jt>>1)*4
        const uint32_t aOff = ((uint32_t)wmG + (jt & 1) * 8u + l7) * (BSTR * 4u)
                            + (jt >> 1) * 16u;
        const uint32_t aHi = smem_u32(sWhi) + aOff;
        const uint32_t aLo = smem_u32(sWlo) + aOff;
        // B packed hi+lo: mats 0,1 from sBhi (cols k,k+4); 2,3 from sBlo
        const uint32_t bOff = ((uint32_t)wnG + l7) * (BSTR * 4u) + (jt & 1) * 16u;
        const uint32_t bAddr = (jt < 2 ? smem_u32(sBhi) : smem_u32(sBlo)) + bOff;
#pragma unroll
        for (int ks = 0; ks < 16; ks++) {
            float* g = (ks & 1) ? gaccB : gaccA;
            uint32_t ah[4], al[4], bb[4];
            ldsm_x4(ah[0], ah[1], ah[2], ah[3], aHi + ks * 32u);
            ldsm_x4(al[0], al[1], al[2], al[3], aLo + ks * 32u);
            ldsm_x4(bb[0], bb[1], bb[2], bb[3], bAddr + ks * 32u);
            mma_split(g, ah, al, &bb[0], &bb[2]);
        }
    }
    float gacc[4];
#pragma unroll
    for (int i = 0; i < 4; i++) gacc[i] = gaccA[i] + gaccB[i];
    __syncthreads();

    {
#pragma unroll
        for (int i = 0; i < 4; i++) {
            const int t = wmG + (lane >> 2) + (i >> 1) * 8;
            const int s = wnG + (lane & 3) * 2 + (i & 1);
            float v = 0.f;
            if (s <= t) v = gacc[i] * s_dt[s] * expf(s_ca[t] - s_ca[s]);
            split_store(v, &sMhi[t*XSTR+s], &sMlo[t*XSTR+s]);
        }
        const int t  = tid & 31;
        const int p0 = (tid >> 5) * 8;
        const float w = s_w[t];
#pragma unroll
        for (int i = 0; i < 8; i++) {
            const int p = p0 + i;
            float v = (sXhi[p*XSTR+t] + sXlo[p*XSTR+t]) * w;
            split_store(v, &sWhi[p*XSTR+t], &sWlo[p*XSTR+t]);
        }
    }
    __syncthreads();

    { // Y_intra = M @ X (32x64x32), LDSM
        const int wm = (warp >> 2) * 16;
        const int wp = (warp & 3) * 16;
        const uint32_t mOff = ((uint32_t)wm + (jt & 1) * 8u + l7) * (XSTR * 4u)
                            + (jt >> 1) * 16u;
        const uint32_t mHi = smem_u32(sMhi) + mOff;
        const uint32_t mLo = smem_u32(sMlo) + mOff;
        // X: mats 0,1 = nt0 rows wp..wp+7 (cols k,k+4); 2,3 = nt1 rows wp+8..+15
        const uint32_t xOff = ((uint32_t)wp + (jt >> 1) * 8u + l7) * (XSTR * 4u)
                            + (jt & 1) * 16u;
        const uint32_t xHi = smem_u32(sXhi) + xOff;
        const uint32_t xLo = smem_u32(sXlo) + xOff;

        float yacc[2][4];
#pragma unroll
        for (int nt = 0; nt < 2; nt++)
#pragma unroll
            for (int i = 0; i < 4; i++) yacc[nt][i] = 0.f;
#pragma unroll
        for (int ks = 0; ks < 4; ks++) {
            uint32_t ah[4], al[4], bhh[4], bll[4];
            ldsm_x4(ah[0], ah[1], ah[2], ah[3], mHi + ks * 32u);
            ldsm_x4(al[0], al[1], al[2], al[3], mLo + ks * 32u);
            ldsm_x4(bhh[0], bhh[1], bhh[2], bhh[3], xHi + ks * 32u);
            ldsm_x4(bll[0], bll[1], bll[2], bll[3], xLo + ks * 32u);
#pragma unroll
            for (int nt = 0; nt < 2; nt++)
                mma_split(yacc[nt], ah, al, &bhh[2*nt], &bll[2*nt]);
        }
        float* yout = g_y + ((size_t)b * Ll + t0) * DINNER + h * 64;
#pragma unroll
        for (int nt = 0; nt < 2; nt++) {
            const int t = wm + (lane >> 2);
            const int p = wp + nt * 8 + (lane & 3) * 2;
            *(float2*)&yout[(size_t)t * DINNER + p]       = make_float2(yacc[nt][0], yacc[nt][1]);
            *(float2*)&yout[(size_t)(t + 8) * DINNER + p] = make_float2(yacc[nt][2], yacc[nt][3]);
        }
    }

    { // S_c = Xw @ B^T (64x128x32): A via LDSM, B scalar (transposed read)
        const int wp = (warp >> 1) * 16;
        const int wn = (warp & 1) * 64;
        const uint32_t awOff = ((uint32_t)wp + (jt & 1) * 8u + l7) * (XSTR * 4u)
                             + (jt >> 1) * 16u;
        const uint32_t awHi = smem_u32(sWhi) + awOff;
        const uint32_t awLo = smem_u32(sWlo) + awOff;

        float sacc[8][4];
#pragma unroll
        for (int nt = 0; nt < 8; nt++)
#pragma unroll
            for (int i = 0; i < 4; i++) sacc[nt][i] = 0.f;
#pragma unroll
        for (int ks = 0; ks < 4; ks++) {
            const int k = ks * 8 + (lane & 3);
            uint32_t ah[4], al[4];
            ldsm_x4(ah[0], ah[1], ah[2], ah[3], awHi + ks * 32u);
            ldsm_x4(al[0], al[1], al[2], al[3], awLo + ks * 32u);
#pragma unroll
            for (int nt = 0; nt < 8; nt++) {
                const int n = wn + nt * 8 + (lane >> 2);
                uint32_t bh2[2], bl2[2];
                bh2[0] = __float_as_uint(sBhi[k*BSTR+n]);     bl2[0] = __float_as_uint(sBlo[k*BSTR+n]);
                bh2[1] = __float_as_uint(sBhi[(k+4)*BSTR+n]); bl2[1] = __float_as_uint(sBlo[(k+4)*BSTR+n]);
                mma_split(sacc[nt], ah, al, bh2, bl2);
            }
        }
        float* sout = g_state + ((size_t)bh * NC + c) * SSTATE;
#pragma unroll
        for (int nt = 0; nt < 8; nt++) {
            const int p = wp + (lane >> 2);
            const int n = wn + nt * 8 + (lane & 3) * 2;
            *(float2*)&sout[(size_t)p * DSTATE + n]       = make_float2(sacc[nt][0], sacc[nt][1]);
            *(float2*)&sout[(size_t)(p + 8) * DSTATE + n] = make_float2(sacc[nt][2], sacc[nt][3]);
        }
    }
}

// ============== SSD K2: inter-chunk exclusive scan; stores tf32-rounded ==============
__global__ __launch_bounds__(256) void ssd_state_scan_kernel()
{
    const int bh = blockIdx.x >> 3;
    const int sl = blockIdx.x & 7;
    const int off = sl * 1024 + threadIdx.x * 4;
    const size_t base = (size_t)bh * NC * SSTATE + off;
    const float* ca = g_ca + (size_t)bh * NC * Q + (Q - 1);

    float4 run = make_float4(0.f, 0.f, 0.f, 0.f);
#pragma unroll 4
    for (int c = 0; c < NC; c++) {
        float4 o;
        o.x = __uint_as_float(f2tf(run.x));
        o.y = __uint_as_float(f2tf(run.y));
        o.z = __uint_as_float(f2tf(run.z));
        o.w = __uint_as_float(f2tf(run.w));
        *(float4*)&g_sprev[base + (size_t)c * SSTATE] = o;
        const float P = expf(ca[(size_t)c * Q]);
        const float4 v = *(const float4*)&g_state[base + (size_t)c * SSTATE];
        run.x = fmaf(run.x, P, v.x);
        run.y = fmaf(run.y, P, v.y);
        run.z = fmaf(run.z, P, v.z);
        run.w = fmaf(run.w, P, v.w);
    }
}

// ============== SSD K3: y += exp(ca)*C@S_prev^T + D*x (LDSM, S hi-only) ==============
__global__ __launch_bounds__(256, 2) void ssd_inter_kernel(const float* __restrict__ Dp)
{
    extern __shared__ float smf[];
    float* sChi = smf;
    float* sClo = sChi + Q * BSTR;
    float* sS   = sClo + Q * BSTR;
    float* s_ca = sS + 64 * BSTR;

    const int tid  = threadIdx.x;
    const int lane = tid & 31;
    const int warp = tid >> 5;
    const int bx = blockIdx.x;
    const int h = bx & 31;
    const int c = (bx >> 5) & (NC - 1);
    const int b = bx >> 12;
    const int t0 = c * Q;
    const int bh = b * NHEADS + h;
    const float* xbase = g_xbc + ((size_t)b * Ll + t0) * CONVDIM;

    {
        const uint32_t base2 = smem_u32(smf);
        const int t  = tid >> 3;
        const int l8 = (tid & 7) * 16;
        const size_t row = (size_t)(b * Ll + t0 + t) * 256;
        const float* hs = g_bcs_hi + row + 128;
        const float* ls = g_bcs_lo + row + 128;
        const uint32_t off = (uint32_t)(t * BSTR + l8) * 4u;
        const uint32_t dC_hi = base2 + off;
        const uint32_t dC_lo = dC_hi + Q * BSTR * 4u;
#pragma unroll
        for (int j = 0; j < 4; j++) {
            asm volatile("cp.async.cg.shared.global [%0], [%1], 16;"
                         :: "r"(dC_hi + j * 16), "l"(hs + l8 + j * 4));
            asm volatile("cp.async.cg.shared.global [%0], [%1], 16;"
                         :: "r"(dC_lo + j * 16), "l"(ls + l8 + j * 4));
        }
        const int p   = tid >> 2;
        const int nsg = (tid & 3) * 32;
        const float* srcS = g_sprev + ((size_t)bh * NC + c) * SSTATE
                          + (size_t)p * DSTATE + nsg;
        const uint32_t dS = base2 + (uint32_t)(2 * Q * BSTR + p * BSTR + nsg) * 4u;
#pragma unroll
        for (int j = 0; j < 8; j++)
            asm volatile("cp.async.cg.shared.global [%0], [%1], 16;"
                         :: "r"(dS + j * 16), "l"(srcS + j * 4));
        asm volatile("cp.async.commit_group;");

        if (tid < 32) s_ca[tid] = g_ca[((size_t)bh * NC + c) * Q + tid];
    }
    asm volatile("cp.async.wait_group 0;");
    __syncthreads();

    const int wm = (warp >> 2) * 16;
    const int wp = (warp & 3) * 16;
    const uint32_t l7 = (uint32_t)(lane & 7);
    const uint32_t jt = (uint32_t)(lane >> 3);

    const uint32_t cOff = ((uint32_t)wm + (jt & 1) * 8u + l7) * (BSTR * 4u)
                        + (jt >> 1) * 16u;
    const uint32_t cHi = smem_u32(sChi) + cOff;
    const uint32_t cLo = smem_u32(sClo) + cOff;
    // S: mats 0,1 = nt0 rows wp..+7 cols k,k+4; 2,3 = nt1 rows wp+8..+15
    const uint32_t sOff = ((uint32_t)wp + (jt >> 1) * 8u + l7) * (BSTR * 4u)
                        + (jt & 1) * 16u;
    const uint32_t sAddr = smem_u32(sS) + sOff;

    float accA[2][4], accB[2][4];
#pragma unroll
    for (int nt = 0; nt < 2; nt++)
#pragma unroll
        for (int i = 0; i < 4; i++) { accA[nt][i] = 0.f; accB[nt][i] = 0.f; }

#pragma unroll
    for (int ks = 0; ks < 16; ks++) {
        uint32_t ah[4], al[4], ss[4];
        ldsm_x4(ah[0], ah[1], ah[2], ah[3], cHi + ks * 32u);
        ldsm_x4(al[0], al[1], al[2], al[3], cLo + ks * 32u);
        ldsm_x4(ss[0], ss[1], ss[2], ss[3], sAddr + ks * 32u);
#pragma unroll
        for (int nt = 0; nt < 2; nt++) {
            float* a = (ks & 1) ? accB[nt] : accA[nt];
            mma_tf32(a, ah, &ss[2*nt]);
            mma_tf32(a, al, &ss[2*nt]);
        }
    }
    float acc[2][4];
#pragma unroll
    for (int nt = 0; nt < 2; nt++)
#pragma unroll
        for (int i = 0; i < 4; i++) acc[nt][i] = accA[nt][i] + accB[nt][i];

    const float Dh = Dp[h];
    float* yout = g_y + ((size_t)b * Ll + t0) * DINNER + h * 64;
    const float* xsrc = xbase + h * 64;
#pragma unroll
    for (int nt = 0; nt < 2; nt++) {
#pragma unroll
        for (int half = 0; half < 2; half++) {
            const int t = wm + (lane >> 2) + half * 8;
            const int p = wp + nt * 8 + (lane & 3) * 2;
            const float e = expf(s_ca[t]);
            float2 xv = *(const float2*)(xsrc + (size_t)t * CONVDIM + p);
            float2 yo = *(float2*)(yout + (size_t)t * DINNER + p);
            yo.x += e * acc[nt][half * 2 + 0] + Dh * xv.x;
            yo.y += e * acc[nt][half * 2 + 1] + Dh * xv.y;
            *(float2*)(yout + (size_t)t * DINNER + p) = yo;
        }
    }
}

// ============== gate + RMSnorm (tf32-rounded out) ==============
__global__ __launch_bounds__(256) void gatenorm_kernel(const float* __restrict__ norm_w)
{
    const int row = blockIdx.x;
    const float* zrow = g_zx + (size_t)row * DIP;
    float* yrow = g_y + (size_t)row * DINNER;

    float v[8];
    float ss = 0.f;
#pragma unroll
    for (int i = 0; i < 8; i++) {
        const int c = threadIdx.x + i * 256;
        float d = yrow[c];
        float z = zrow[c];
        float g = d * (z / (1.f + expf(-z)));
        v[i] = g;
        ss = fmaf(g, g, ss);
    }
#pragma unroll
    for (int o = 16; o; o >>= 1) ss += __shfl_xor_sync(0xffffffffu, ss, o);

    __shared__ float red[8];
    if ((threadIdx.x & 31) == 0) red[threadIdx.x >> 5] = ss;
    __syncthreads();
    float tot = 0.f;
#pragma unroll
    for (int w = 0; w < 8; w++) tot += red[w];
    const float scale = rsqrtf(tot * (1.f / (float)DINNER) + 1e-5f);

#pragma unroll
    for (int i = 0; i < 8; i++) {
        const int c = threadIdx.x + i * 256;
        yrow[c] = __uint_as_float(f2tf(v[i] * scale * norm_w[c]));
    }
}

// ============== launch ==============
extern "C" void kernel_launch(void* const* d_in, const int* in_sizes, int n_in,
                              void* d_out, int out_size)
{
    const float* x          = (const float*)d_in[0];
    const float* in_proj_w  = (const float*)d_in[1];
    const float* conv_w     = (const float*)d_in[2];
    const float* conv_b     = (const float*)d_in[3];
    const float* dt_bias    = (const float*)d_in[4];
    const float* A_log      = (const float*)d_in[5];
    const float* Dp         = (const float*)d_in[6];
    const float* norm_w     = (const float*)d_in[7];
    const float* out_proj_w = (const float*)d_in[8];
    float* out = (float*)d_out;

    float *zx, *yb, *xc, *w1, *w2;
    cudaGetSymbolAddress((void**)&zx, g_zx);
    cudaGetSymbolAddress((void**)&yb, g_y);
    cudaGetSymbolAddress((void**)&xc, g_xc);
    cudaGetSymbolAddress((void**)&w1, g_w1);
    cudaGetSymbolAddress((void**)&w2, g_w2);

    const int gemm_smem = 3 * TSTAGE_B;
    const int k1_smem = (4 * Q * BSTR + 2 * 64 * XSTR + 2 * Q * XSTR + 3 * Q) * 4;
    const int k3_smem = (2 * Q * BSTR + 64 * BSTR + Q) * 4;
    cudaFuncSetAttribute(gemm_tf32_ca_kernel,
                         cudaFuncAttributeMaxDynamicSharedMemorySize, gemm_smem);
    cudaFuncSetAttribute(ssd_chunk_kernel,
                         cudaFuncAttributeMaxDynamicSharedMemorySize, k1_smem);
    cudaFuncSetAttribute(ssd_inter_kernel,
                         cudaFuncAttributeMaxDynamicSharedMemorySize, k3_smem);

    {
        int n4;
        n4 = (BL * DMODEL) / 4;
        cvt_tf32_kernel<<<(n4 + 255) / 256, 256>>>(x, xc, n4);
        n4 = (DIP * DMODEL) / 4;
        cvt_tf32_kernel<<<(n4 + 255) / 256, 256>>>(in_proj_w, w1, n4);
        n4 = (DOUT * DINNER) / 4;
        cvt_tf32_kernel<<<(n4 + 255) / 256, 256>>>(out_proj_w, w2, n4);
    }
    {
        dim3 grid((DIP + 127) / 128, BL / 128);
        gemm_tf32_ca_kernel<<<grid, 256, gemm_smem>>>(xc, w1, zx, BL, DIP, DMODEL);
    }
    {
        const int total = BL * (CONVDIM / 4);
        conv_silu_kernel<<<(total + 255) / 256, 256>>>(conv_w, conv_b);
    }
    dt_kernel<<<(BL * NHEADS) / 256, 256>>>(dt_bias, A_log);
    ssd_chunk_kernel<<<Bb * NC * NHEADS, 256, k1_smem>>>();
    ssd_state_scan_kernel<<<Bb * NHEADS * 8, 256>>>();
    ssd_inter_kernel<<<Bb * NC * NHEADS, 256, k3_smem>>>(Dp);
    gatenorm_kernel<<<BL, 256>>>(norm_w);
    {
        dim3 grid(DOUT / 128, BL / 128);
        gemm_tf32_ca_kernel<<<grid, 256, gemm_smem>>>(yb, w2, out, BL, DOUT, DINNER);
    }
}

// round 17
// speedup vs baseline: 1.0486x; 1.0486x over previous
#include <cuda_runtime.h>
#include <math.h>
#include <stdint.h>

#define Bb      2
#define Ll      4096
#define DMODEL  1024
#define DINNER  2048
#define NHEADS  32
#define HEADDIM 64
#define DSTATE  128
#define DIP     4384
#define CONVDIM 2304
#define BL      (Bb*Ll)
#define DOUT    1024
#define Q       32
#define NC      (Ll/Q)
#define SSTATE  (HEADDIM*DSTATE)
#define BSTR    132
#define XSTR    36

__device__ float g_zx    [(size_t)BL * DIP];
__device__ float g_xbc   [(size_t)BL * CONVDIM];
__device__ float g_y     [(size_t)BL * DINNER];
__device__ float g_dt    [BL * NHEADS];
__device__ float g_dA    [BL * NHEADS];
__device__ float g_xc    [(size_t)BL * DMODEL];
__device__ float g_w1    [(size_t)DIP * DMODEL];
__device__ float g_w2    [(size_t)DOUT * DINNER];
__device__ float g_state [(size_t)Bb*NHEADS * NC * SSTATE];
__device__ float g_sprev [(size_t)Bb*NHEADS * NC * SSTATE];
__device__ float g_ca    [(size_t)Bb*NHEADS * NC * Q];
__device__ float g_bcs_hi[(size_t)BL * 256];
__device__ float g_bcs_lo[(size_t)BL * 256];
__device__ float g_G     [(size_t)Bb * NC * Q * Q];   // head-independent C@B^T

__device__ __forceinline__ uint32_t f2tf(float f) {
    uint32_t r; asm("cvt.rna.tf32.f32 %0, %1;" : "=r"(r) : "f"(f)); return r;
}
__device__ __forceinline__ void split_store(float v, float* hi, float* lo) {
    float h = __uint_as_float(f2tf(v));
    *hi = h; *lo = __uint_as_float(f2tf(v - h));
}
__device__ __forceinline__ void mma_tf32(float c[4], const uint32_t a[4], const uint32_t b[2]) {
    asm volatile(
        "mma.sync.aligned.m16n8k8.row.col.f32.tf32.tf32.f32 "
        "{%0,%1,%2,%3}, {%4,%5,%6,%7}, {%8,%9}, {%0,%1,%2,%3};"
        : "+f"(c[0]), "+f"(c[1]), "+f"(c[2]), "+f"(c[3])
        : "r"(a[0]), "r"(a[1]), "r"(a[2]), "r"(a[3]), "r"(b[0]), "r"(b[1]));
}
__device__ __forceinline__ void mma_split(float c[4], const uint32_t ah[4], const uint32_t al[4],
                                          const uint32_t bh[2], const uint32_t bl[2]) {
    mma_tf32(c, ah, bh); mma_tf32(c, ah, bl); mma_tf32(c, al, bh);
}
__device__ __forceinline__ void ldsm_x4(uint32_t& r0, uint32_t& r1, uint32_t& r2, uint32_t& r3,
                                        uint32_t addr) {
    asm volatile("ldmatrix.sync.aligned.m8n8.x4.shared.b16 {%0,%1,%2,%3}, [%4];"
                 : "=r"(r0), "=r"(r1), "=r"(r2), "=r"(r3) : "r"(addr));
}
__device__ __forceinline__ uint32_t smem_u32(const void* p) {
    return (uint32_t)__cvta_generic_to_shared(p);
}

__global__ __launch_bounds__(256) void cvt_tf32_kernel(
    const float* __restrict__ src, float* __restrict__ dst, int n4)
{
    const int i = blockIdx.x * blockDim.x + threadIdx.x;
    if (i >= n4) return;
    float4 v = ((const float4*)src)[i];
    uint4 u;
    u.x = f2tf(v.x); u.y = f2tf(v.y); u.z = f2tf(v.z); u.w = f2tf(v.w);
    ((uint4*)dst)[i] = u;
}

// ============== TF32 GEMM (NT): 3-stage cp.async, SW128 smem, LDSM (R15) ==============
#define TSTAGE_F 4096
#define TSTAGE_B (2 * TSTAGE_F * 4)

__global__ __launch_bounds__(256, 2) void gemm_tf32_ca_kernel(
    const float* __restrict__ A, const float* __restrict__ Bw,
    float* __restrict__ C, int M, int N, int K)
{
    extern __shared__ float sm[];

    const int tid  = threadIdx.x;
    const int lane = tid & 31;
    const int warp = tid >> 5;
    const int wm = (warp >> 2) * 64;
    const int wn = (warp & 3) * 32;
    const int bm = blockIdx.y * 128;
    const int bn = blockIdx.x * 128;

    const int r    = tid >> 1;
    const int ccol = (tid & 1) * 16;
    uint32_t doff[4];
#pragma unroll
    for (int j = 0; j < 4; j++) {
        const uint32_t lc = (uint32_t)((tid & 1) * 4 + j);
        doff[j] = (uint32_t)r * 128u + ((lc ^ ((uint32_t)r & 7u)) * 16u);
    }
    const float* Ag = A  + (size_t)(bm + r) * K + ccol;
    const float* Bg = Bw + (size_t)(bn + r) * K + ccol;
    const int bsz = ((bn + r) < N) ? 16 : 0;
    const uint32_t sbase = smem_u32(sm);

#define G_ISSUE(kt, s) do {                                                    \
        const float* ag_ = Ag + (size_t)(kt) * 32;                             \
        const float* bg_ = Bg + (size_t)(kt) * 32;                             \
        const uint32_t da_ = sbase + (uint32_t)(s) * TSTAGE_B;                 \
        const uint32_t db_ = da_ + TSTAGE_F * 4;                               \
        _Pragma("unroll")                                                      \
        for (int j_ = 0; j_ < 4; j_++)                                         \
            asm volatile("cp.async.cg.shared.global [%0], [%1], 16;"           \
                         :: "r"(da_ + doff[j_]), "l"(ag_ + j_ * 4));           \
        _Pragma("unroll")                                                      \
        for (int j_ = 0; j_ < 4; j_++)                                         \
            asm volatile("cp.async.cg.shared.global [%0], [%1], 16, %2;"       \
                         :: "r"(db_ + doff[j_]), "l"(bg_ + j_ * 4), "r"(bsz)); \
        asm volatile("cp.async.commit_group;");                                \
    } while (0)

    float acc[4][4][4];
#pragma unroll
    for (int mt = 0; mt < 4; mt++)
#pragma unroll
        for (int nt = 0; nt < 4; nt++)
#pragma unroll
            for (int i = 0; i < 4; i++) acc[mt][nt][i] = 0.f;

    const uint32_t x7   = (uint32_t)(lane & 7);
    const uint32_t aRow = x7 + (uint32_t)((lane >> 3) & 1) * 8u;
    const uint32_t aE   = (uint32_t)(lane >> 4);
    const uint32_t bRow = x7 + (uint32_t)(lane >> 4) * 8u;
    const uint32_t bE   = (uint32_t)((lane >> 3) & 1);

    const int KT = K / 32;

    G_ISSUE(0, 0);
    G_ISSUE(1, 1);

    for (int kt = 0; kt < KT; kt++) {
        if (kt + 1 < KT) asm volatile("cp.async.wait_group 1;");
        else             asm volatile("cp.async.wait_group 0;");
        __syncthreads();
        if (kt + 2 < KT) G_ISSUE(kt + 2, (kt + 2) % 3);

        const uint32_t aStage = sbase + (uint32_t)(kt % 3) * TSTAGE_B;
        const uint32_t bStage = aStage + TSTAGE_F * 4;
        uint32_t aBase[4], bBase[2];
#pragma unroll
        for (int mt = 0; mt < 4; mt++)
            aBase[mt] = aStage + (uint32_t)(wm + mt * 16 + aRow) * 128u;
#pragma unroll
        for (int np = 0; np < 2; np++)
            bBase[np] = bStage + (uint32_t)(wn + np * 16 + bRow) * 128u;

#pragma unroll
        for (int ks = 0; ks < 4; ks++) {
            const uint32_t ka = (((uint32_t)(2 * ks) + aE) ^ x7) * 16u;
            const uint32_t kb = (((uint32_t)(2 * ks) + bE) ^ x7) * 16u;
            uint32_t af[4][4];
#pragma unroll
            for (int mt = 0; mt < 4; mt++)
                ldsm_x4(af[mt][0], af[mt][1], af[mt][2], af[mt][3], aBase[mt] + ka);
            uint32_t bf[4][2];
#pragma unroll
            for (int np = 0; np < 2; np++)
                ldsm_x4(bf[2*np][0], bf[2*np][1], bf[2*np+1][0], bf[2*np+1][1],
                        bBase[np] + kb);
#pragma unroll
            for (int mt = 0; mt < 4; mt++)
#pragma unroll
                for (int nt = 0; nt < 4; nt++)
                    mma_tf32(acc[mt][nt], af[mt], bf[nt]);
        }
    }

#pragma unroll
    for (int mt = 0; mt < 4; mt++) {
        const int row = bm + wm + mt * 16 + (lane >> 2);
#pragma unroll
        for (int nt = 0; nt < 4; nt++) {
            const int col = bn + wn + nt * 8 + (lane & 3) * 2;
            if (col < N) {
                *(float2*)&C[(size_t)row * N + col]       = make_float2(acc[mt][nt][0], acc[mt][nt][1]);
                *(float2*)&C[(size_t)(row + 8) * N + col] = make_float2(acc[mt][nt][2], acc[mt][nt][3]);
            }
        }
    }
#undef G_ISSUE
}

// ============== depthwise conv + SiLU + pre-split B/C ==============
__global__ __launch_bounds__(256) void conv_silu_kernel(
    const float* __restrict__ conv_w, const float* __restrict__ conv_b)
{
    const int idx = blockIdx.x * blockDim.x + threadIdx.x;
    if (idx >= BL * (CONVDIM / 4)) return;
    const int c4 = (idx % (CONVDIM / 4)) * 4;
    const int bl = idx / (CONVDIM / 4);
    const int l  = bl & (Ll - 1);

    float4 acc = *(const float4*)(conv_b + c4);
    float4 w0 = *(const float4*)(conv_w + (c4 + 0) * 4);
    float4 w1 = *(const float4*)(conv_w + (c4 + 1) * 4);
    float4 w2 = *(const float4*)(conv_w + (c4 + 2) * 4);
    float4 w3 = *(const float4*)(conv_w + (c4 + 3) * 4);

    const float* col = g_zx + (size_t)bl * DIP + DINNER + c4;
#pragma unroll
    for (int j = 0; j < 4; j++) {
        const int ls = l - 3 + j;
        if (ls >= 0) {
            float4 v = *(const float4*)(col + (long)(j - 3) * DIP);
            acc.x = fmaf(v.x, (&w0.x)[j], acc.x);
            acc.y = fmaf(v.y, (&w1.x)[j], acc.y);
            acc.z = fmaf(v.z, (&w2.x)[j], acc.z);
            acc.w = fmaf(v.w, (&w3.x)[j], acc.w);
        }
    }
    float4 o;
    o.x = acc.x / (1.f + expf(-acc.x));
    o.y = acc.y / (1.f + expf(-acc.y));
    o.z = acc.z / (1.f + expf(-acc.z));
    o.w = acc.w / (1.f + expf(-acc.w));

    if (c4 < DINNER) {
        *(float4*)(g_xbc + (size_t)bl * CONVDIM + c4) = o;
    } else {
        const int q = c4 - DINNER;
        float4 h4, l4;
        h4.x = __uint_as_float(f2tf(o.x)); l4.x = __uint_as_float(f2tf(o.x - h4.x));
        h4.y = __uint_as_float(f2tf(o.y)); l4.y = __uint_as_float(f2tf(o.y - h4.y));
        h4.z = __uint_as_float(f2tf(o.z)); l4.z = __uint_as_float(f2tf(o.z - h4.z));
        h4.w = __uint_as_float(f2tf(o.w)); l4.w = __uint_as_float(f2tf(o.w - h4.w));
        *(float4*)(g_bcs_hi + (size_t)bl * 256 + q) = h4;
        *(float4*)(g_bcs_lo + (size_t)bl * 256 + q) = l4;
    }
}

// ============== dt: softplus; a = dt * (-exp(A_log)) ==============
__global__ __launch_bounds__(256) void dt_kernel(
    const float* __restrict__ dt_bias, const float* __restrict__ A_log)
{
    const int idx = blockIdx.x * blockDim.x + threadIdx.x;
    if (idx >= BL * NHEADS) return;
    const int h  = idx & (NHEADS - 1);
    const int bl = idx >> 5;
    float raw = g_zx[(size_t)bl * DIP + DINNER + CONVDIM + h] + dt_bias[h];
    float dt = (raw > 20.f) ? raw : log1pf(expf(raw));
    float A = -expf(A_log[h]);
    g_dt[idx] = dt;
    g_dA[idx] = dt * A;
}

// ============== SSD G: G = C @ B^T per (b, chunk) — head-independent ==============
__global__ __launch_bounds__(256) void ssd_g_kernel()
{
    extern __shared__ float smf[];
    float* sBhi = smf;
    float* sBlo = sBhi + Q * BSTR;
    float* sChi = sBlo + Q * BSTR;
    float* sClo = sChi + Q * BSTR;

    const int tid  = threadIdx.x;
    const int lane = tid & 31;
    const int warp = tid >> 5;
    const int bx = blockIdx.x;
    const int c = bx & (NC - 1);
    const int b = bx >> 7;
    const int t0 = c * Q;

    {
        const int t  = tid >> 3;
        const int l8 = (tid & 7) * 16;
        const size_t row = (size_t)(b * Ll + t0 + t) * 256;
        const float* hs = g_bcs_hi + row;
        const float* ls = g_bcs_lo + row;
        const uint32_t base = smem_u32(smf);
        const uint32_t off = (uint32_t)(t * BSTR + l8) * 4u;
        const uint32_t dB_hi = base + off;
        const uint32_t dB_lo = dB_hi + Q * BSTR * 4u;
        const uint32_t dC_hi = dB_lo + Q * BSTR * 4u;
        const uint32_t dC_lo = dC_hi + Q * BSTR * 4u;
#pragma unroll
        for (int j = 0; j < 4; j++) {
            asm volatile("cp.async.cg.shared.global [%0], [%1], 16;"
                         :: "r"(dB_hi + j * 16), "l"(hs + l8 + j * 4));
            asm volatile("cp.async.cg.shared.global [%0], [%1], 16;"
                         :: "r"(dB_lo + j * 16), "l"(ls + l8 + j * 4));
            asm volatile("cp.async.cg.shared.global [%0], [%1], 16;"
                         :: "r"(dC_hi + j * 16), "l"(hs + 128 + l8 + j * 4));
            asm volatile("cp.async.cg.shared.global [%0], [%1], 16;"
                         :: "r"(dC_lo + j * 16), "l"(ls + 128 + l8 + j * 4));
        }
        asm volatile("cp.async.commit_group;");
    }
    asm volatile("cp.async.wait_group 0;");
    __syncthreads();

    const int wmG = (warp >> 2) * 16;
    const int wnG = (warp & 3) * 8;
    float gaccA[4] = {0.f, 0.f, 0.f, 0.f};
    float gaccB[4] = {0.f, 0.f, 0.f, 0.f};
#pragma unroll
    for (int ks = 0; ks < 16; ks++) {
        float* g = (ks & 1) ? gaccB : gaccA;
        const int k = ks * 8 + (lane & 3);
        const int m = wmG + (lane >> 2);
        uint32_t ah[4], al[4];
        ah[0] = __float_as_uint(sChi[m*BSTR+k]);     al[0] = __float_as_uint(sClo[m*BSTR+k]);
        ah[1] = __float_as_uint(sChi[(m+8)*BSTR+k]); al[1] = __float_as_uint(sClo[(m+8)*BSTR+k]);
        ah[2] = __float_as_uint(sChi[m*BSTR+k+4]);   al[2] = __float_as_uint(sClo[m*BSTR+k+4]);
        ah[3] = __float_as_uint(sChi[(m+8)*BSTR+k+4]);al[3] = __float_as_uint(sClo[(m+8)*BSTR+k+4]);
        const int n = wnG + (lane >> 2);
        uint32_t bh2[2], bl2[2];
        bh2[0] = __float_as_uint(sBhi[n*BSTR+k]);    bl2[0] = __float_as_uint(sBlo[n*BSTR+k]);
        bh2[1] = __float_as_uint(sBhi[n*BSTR+k+4]);  bl2[1] = __float_as_uint(sBlo[n*BSTR+k+4]);
        mma_split(g, ah, al, bh2, bl2);
    }
    float* gout = g_G + (size_t)(b * NC + c) * Q * Q;
#pragma unroll
    for (int i = 0; i < 4; i++) {
        const int t = wmG + (lane >> 2) + (i >> 1) * 8;
        const int s = wnG + (lane & 3) * 2 + (i & 1);
        gout[t * Q + s] = gaccA[i] + gaccB[i];
    }
}

// ============== SSD K1: M build + Y_intra + S_c (G precomputed) ==============
__global__ __launch_bounds__(256, 2) void ssd_chunk_kernel()
{
    extern __shared__ float smf[];
    float* sBhi = smf;
    float* sBlo = sBhi + Q * BSTR;
    float* sWhi = sBlo + Q * BSTR;   // Xw [64][XSTR]
    float* sWlo = sWhi + 64 * XSTR;
    float* sXhi = sWlo + 64 * XSTR;  // Xt [64][XSTR]
    float* sXlo = sXhi + 64 * XSTR;
    float* sMhi = sXlo + 64 * XSTR;  // [Q][XSTR]
    float* sMlo = sMhi + Q * XSTR;
    float* s_dt = sMlo + Q * XSTR;
    float* s_ca = s_dt + Q;
    float* s_w  = s_ca + Q;

    const int tid  = threadIdx.x;
    const int lane = tid & 31;
    const int warp = tid >> 5;
    const int bx = blockIdx.x;
    const int h = bx & 31;
    const int c = (bx >> 5) & (NC - 1);
    const int b = bx >> 12;
    const int t0 = c * Q;
    const int bh = b * NHEADS + h;
    const float* xbase = g_xbc + ((size_t)b * Ll + t0) * CONVDIM;

    // ---- early G fetch (head-independent, precomputed) ----
    const int wmG = (warp >> 2) * 16;
    const int wnG = (warp & 3) * 8;
    float gacc[4];
    {
        const float* gbase = g_G + (size_t)(b * NC + c) * Q * Q;
#pragma unroll
        for (int i = 0; i < 4; i++) {
            const int t = wmG + (lane >> 2) + (i >> 1) * 8;
            const int s = wnG + (lane & 3) * 2 + (i & 1);
            gacc[i] = gbase[t * Q + s];
        }
    }

    // ---- async staging of pre-split B only ----
    {
        const int t  = tid >> 3;
        const int l8 = (tid & 7) * 16;
        const size_t row = (size_t)(b * Ll + t0 + t) * 256;
        const float* hs = g_bcs_hi + row;
        const float* ls = g_bcs_lo + row;
        const uint32_t base = smem_u32(smf);
        const uint32_t off = (uint32_t)(t * BSTR + l8) * 4u;
        const uint32_t dB_hi = base + off;
        const uint32_t dB_lo = dB_hi + Q * BSTR * 4u;
#pragma unroll
        for (int j = 0; j < 4; j++) {
            asm volatile("cp.async.cg.shared.global [%0], [%1], 16;"
                         :: "r"(dB_hi + j * 16), "l"(hs + l8 + j * 4));
            asm volatile("cp.async.cg.shared.global [%0], [%1], 16;"
                         :: "r"(dB_lo + j * 16), "l"(ls + l8 + j * 4));
        }
        asm volatile("cp.async.commit_group;");
    }
    // ---- X staging (conflict-free transpose) ----
    {
        const int t  = tid & 31;
        const int p0 = (tid >> 5) * 8;
        const float4* srcX = (const float4*)(xbase + (size_t)t * CONVDIM + h * 64 + p0);
        float4 v0 = srcX[0];
        float4 v1 = srcX[1];
        split_store(v0.x, &sXhi[(p0+0)*XSTR+t], &sXlo[(p0+0)*XSTR+t]);
        split_store(v0.y, &sXhi[(p0+1)*XSTR+t], &sXlo[(p0+1)*XSTR+t]);
        split_store(v0.z, &sXhi[(p0+2)*XSTR+t], &sXlo[(p0+2)*XSTR+t]);
        split_store(v0.w, &sXhi[(p0+3)*XSTR+t], &sXlo[(p0+3)*XSTR+t]);
        split_store(v1.x, &sXhi[(p0+4)*XSTR+t], &sXlo[(p0+4)*XSTR+t]);
        split_store(v1.y, &sXhi[(p0+5)*XSTR+t], &sXlo[(p0+5)*XSTR+t]);
        split_store(v1.z, &sXhi[(p0+6)*XSTR+t], &sXlo[(p0+6)*XSTR+t]);
        split_store(v1.w, &sXhi[(p0+7)*XSTR+t], &sXlo[(p0+7)*XSTR+t]);
    }
    if (tid < 32) {
        const size_t rb = ((size_t)b * Ll + t0 + tid) * NHEADS + h;
        const float dtv = g_dt[rb];
        float cum = g_dA[rb];
        s_dt[tid] = dtv;
#pragma unroll
        for (int o = 1; o < 32; o <<= 1) {
            float nb = __shfl_up_sync(0xffffffffu, cum, o);
            if (tid >= o) cum += nb;
        }
        s_ca[tid] = cum;
        g_ca[((size_t)bh * NC + c) * Q + tid] = cum;
        const float tot = __shfl_sync(0xffffffffu, cum, 31);
        s_w[tid] = dtv * expf(tot - cum);
    }
    asm volatile("cp.async.wait_group 0;");
    __syncthreads();

    // ---- build M (from fetched G); build Xw ----
    {
#pragma unroll
        for (int i = 0; i < 4; i++) {
            const int t = wmG + (lane >> 2) + (i >> 1) * 8;
            const int s = wnG + (lane & 3) * 2 + (i & 1);
            float v = 0.f;
            if (s <= t) v = gacc[i] * s_dt[s] * expf(s_ca[t] - s_ca[s]);
            split_store(v, &sMhi[t*XSTR+s], &sMlo[t*XSTR+s]);
        }
        const int t  = tid & 31;
        const int p0 = (tid >> 5) * 8;
        const float w = s_w[t];
#pragma unroll
        for (int i = 0; i < 8; i++) {
            const int p = p0 + i;
            float v = (sXhi[p*XSTR+t] + sXlo[p*XSTR+t]) * w;
            split_store(v, &sWhi[p*XSTR+t], &sWlo[p*XSTR+t]);
        }
    }
    __syncthreads();

    { // Y_intra = M @ X (32x64x32)
        const int wm = (warp >> 2) * 16;
        const int wp = (warp & 3) * 16;
        float yacc[2][4];
#pragma unroll
        for (int nt = 0; nt < 2; nt++)
#pragma unroll
            for (int i = 0; i < 4; i++) yacc[nt][i] = 0.f;
#pragma unroll
        for (int ks = 0; ks < 4; ks++) {
            const int k = ks * 8 + (lane & 3);
            const int m = wm + (lane >> 2);
            uint32_t ah[4], al[4];
            ah[0] = __float_as_uint(sMhi[m*XSTR+k]);      al[0] = __float_as_uint(sMlo[m*XSTR+k]);
            ah[1] = __float_as_uint(sMhi[(m+8)*XSTR+k]);  al[1] = __float_as_uint(sMlo[(m+8)*XSTR+k]);
            ah[2] = __float_as_uint(sMhi[m*XSTR+k+4]);    al[2] = __float_as_uint(sMlo[m*XSTR+k+4]);
            ah[3] = __float_as_uint(sMhi[(m+8)*XSTR+k+4]);al[3] = __float_as_uint(sMlo[(m+8)*XSTR+k+4]);
#pragma unroll
            for (int nt = 0; nt < 2; nt++) {
                const int p = wp + nt * 8 + (lane >> 2);
                uint32_t bh2[2], bl2[2];
                bh2[0] = __float_as_uint(sXhi[p*XSTR+k]);   bl2[0] = __float_as_uint(sXlo[p*XSTR+k]);
                bh2[1] = __float_as_uint(sXhi[p*XSTR+k+4]); bl2[1] = __float_as_uint(sXlo[p*XSTR+k+4]);
                mma_split(yacc[nt], ah, al, bh2, bl2);
            }
        }
        float* yout = g_y + ((size_t)b * Ll + t0) * DINNER + h * 64;
#pragma unroll
        for (int nt = 0; nt < 2; nt++) {
            const int t = wm + (lane >> 2);
            const int p = wp + nt * 8 + (lane & 3) * 2;
            *(float2*)&yout[(size_t)t * DINNER + p]       = make_float2(yacc[nt][0], yacc[nt][1]);
            *(float2*)&yout[(size_t)(t + 8) * DINNER + p] = make_float2(yacc[nt][2], yacc[nt][3]);
        }
    }

    { // S_c = Xw @ B^T (64x128x32)
        const int wp = (warp >> 1) * 16;
        const int wn = (warp & 1) * 64;
        float sacc[8][4];
#pragma unroll
        for (int nt = 0; nt < 8; nt++)
#pragma unroll
            for (int i = 0; i < 4; i++) sacc[nt][i] = 0.f;
#pragma unroll
        for (int ks = 0; ks < 4; ks++) {
            const int k = ks * 8 + (lane & 3);
            const int m = wp + (lane >> 2);
            uint32_t ah[4], al[4];
            ah[0] = __float_as_uint(sWhi[m*XSTR+k]);      al[0] = __float_as_uint(sWlo[m*XSTR+k]);
            ah[1] = __float_as_uint(sWhi[(m+8)*XSTR+k]);  al[1] = __float_as_uint(sWlo[(m+8)*XSTR+k]);
            ah[2] = __float_as_uint(sWhi[m*XSTR+k+4]);    al[2] = __float_as_uint(sWlo[m*XSTR+k+4]);
            ah[3] = __float_as_uint(sWhi[(m+8)*XSTR+k+4]);al[3] = __float_as_uint(sWlo[(m+8)*XSTR+k+4]);
#pragma unroll
            for (int nt = 0; nt < 8; nt++) {
                const int n = wn + nt * 8 + (lane >> 2);
                uint32_t bh2[2], bl2[2];
                bh2[0] = __float_as_uint(sBhi[k*BSTR+n]);     bl2[0] = __float_as_uint(sBlo[k*BSTR+n]);
                bh2[1] = __float_as_uint(sBhi[(k+4)*BSTR+n]); bl2[1] = __float_as_uint(sBlo[(k+4)*BSTR+n]);
                mma_split(sacc[nt], ah, al, bh2, bl2);
            }
        }
        float* sout = g_state + ((size_t)bh * NC + c) * SSTATE;
#pragma unroll
        for (int nt = 0; nt < 8; nt++) {
            const int p = wp + (lane >> 2);
            const int n = wn + nt * 8 + (lane & 3) * 2;
            *(float2*)&sout[(size_t)p * DSTATE + n]       = make_float2(sacc[nt][0], sacc[nt][1]);
            *(float2*)&sout[(size_t)(p + 8) * DSTATE + n] = make_float2(sacc[nt][2], sacc[nt][3]);
        }
    }
}

// ============== SSD K2: inter-chunk exclusive scan; stores tf32-rounded ==============
__global__ __launch_bounds__(256) void ssd_state_scan_kernel()
{
    const int bh = blockIdx.x >> 3;
    const int sl = blockIdx.x & 7;
    const int off = sl * 1024 + threadIdx.x * 4;
    const size_t base = (size_t)bh * NC * SSTATE + off;
    const float* ca = g_ca + (size_t)bh * NC * Q + (Q - 1);

    float4 run = make_float4(0.f, 0.f, 0.f, 0.f);
#pragma unroll 4
    for (int c = 0; c < NC; c++) {
        float4 o;
        o.x = __uint_as_float(f2tf(run.x));
        o.y = __uint_as_float(f2tf(run.y));
        o.z = __uint_as_float(f2tf(run.z));
        o.w = __uint_as_float(f2tf(run.w));
        *(float4*)&g_sprev[base + (size_t)c * SSTATE] = o;
        const float P = expf(ca[(size_t)c * Q]);
        const float4 v = *(const float4*)&g_state[base + (size_t)c * SSTATE];
        run.x = fmaf(run.x, P, v.x);
        run.y = fmaf(run.y, P, v.y);
        run.z = fmaf(run.z, P, v.z);
        run.w = fmaf(run.w, P, v.w);
    }
}

// ============== SSD K3: y += exp(ca)*C@S_prev^T + D*x (S hi-only, scalar) ==============
__global__ __launch_bounds__(256, 2) void ssd_inter_kernel(const float* __restrict__ Dp)
{
    extern __shared__ float smf[];
    float* sChi = smf;
    float* sClo = sChi + Q * BSTR;
    float* sS   = sClo + Q * BSTR;
    float* s_ca = sS + 64 * BSTR;

    const int tid  = threadIdx.x;
    const int lane = tid & 31;
    const int warp = tid >> 5;
    const int bx = blockIdx.x;
    const int h = bx & 31;
    const int c = (bx >> 5) & (NC - 1);
    const int b = bx >> 12;
    const int t0 = c * Q;
    const int bh = b * NHEADS + h;
    const float* xbase = g_xbc + ((size_t)b * Ll + t0) * CONVDIM;

    {
        const uint32_t base2 = smem_u32(smf);
        const int t  = tid >> 3;
        const int l8 = (tid & 7) * 16;
        const size_t row = (size_t)(b * Ll + t0 + t) * 256;
        const float* hs = g_bcs_hi + row + 128;
        const float* ls = g_bcs_lo + row + 128;
        const uint32_t off = (uint32_t)(t * BSTR + l8) * 4u;
        const uint32_t dC_hi = base2 + off;
        const uint32_t dC_lo = dC_hi + Q * BSTR * 4u;
#pragma unroll
        for (int j = 0; j < 4; j++) {
            asm volatile("cp.async.cg.shared.global [%0], [%1], 16;"
                         :: "r"(dC_hi + j * 16), "l"(hs + l8 + j * 4));
            asm volatile("cp.async.cg.shared.global [%0], [%1], 16;"
                         :: "r"(dC_lo + j * 16), "l"(ls + l8 + j * 4));
        }
        const int p   = tid >> 2;
        const int nsg = (tid & 3) * 32;
        const float* srcS = g_sprev + ((size_t)bh * NC + c) * SSTATE
                          + (size_t)p * DSTATE + nsg;
        const uint32_t dS = base2 + (uint32_t)(2 * Q * BSTR + p * BSTR + nsg) * 4u;
#pragma unroll
        for (int j = 0; j < 8; j++)
            asm volatile("cp.async.cg.shared.global [%0], [%1], 16;"
                         :: "r"(dS + j * 16), "l"(srcS + j * 4));
        asm volatile("cp.async.commit_group;");

        if (tid < 32) s_ca[tid] = g_ca[((size_t)bh * NC + c) * Q + tid];
    }
    asm volatile("cp.async.wait_group 0;");
    __syncthreads();

    const int wm = (warp >> 2) * 16;
    const int wp = (warp & 3) * 16;
    float accA[2][4], accB[2][4];
#pragma unroll
    for (int nt = 0; nt < 2; nt++)
#pragma unroll
        for (int i = 0; i < 4; i++) { accA[nt][i] = 0.f; accB[nt][i] = 0.f; }

#pragma unroll
    for (int ks = 0; ks < 16; ks++) {
        const int k = ks * 8 + (lane & 3);
        const int m = wm + (lane >> 2);
        uint32_t ah[4], al[4];
        ah[0] = __float_as_uint(sChi[m*BSTR+k]);      al[0] = __float_as_uint(sClo[m*BSTR+k]);
        ah[1] = __float_as_uint(sChi[(m+8)*BSTR+k]);  al[1] = __float_as_uint(sClo[(m+8)*BSTR+k]);
        ah[2] = __float_as_uint(sChi[m*BSTR+k+4]);    al[2] = __float_as_uint(sClo[m*BSTR+k+4]);
        ah[3] = __float_as_uint(sChi[(m+8)*BSTR+k+4]);al[3] = __float_as_uint(sClo[(m+8)*BSTR+k+4]);
#pragma unroll
        for (int nt = 0; nt < 2; nt++) {
            const int p = wp + nt * 8 + (lane >> 2);
            uint32_t bh2[2];
            bh2[0] = __float_as_uint(sS[p*BSTR+k]);
            bh2[1] = __float_as_uint(sS[p*BSTR+k+4]);
            float* a = (ks & 1) ? accB[nt] : accA[nt];
            mma_tf32(a, ah, bh2);
            mma_tf32(a, al, bh2);
        }
    }
    float acc[2][4];
#pragma unroll
    for (int nt = 0; nt < 2; nt++)
#pragma unroll
        for (int i = 0; i < 4; i++) acc[nt][i] = accA[nt][i] + accB[nt][i];

    const float Dh = Dp[h];
    float* yout = g_y + ((size_t)b * Ll + t0) * DINNER + h * 64;
    const float* xsrc = xbase + h * 64;
#pragma unroll
    for (int nt = 0; nt < 2; nt++) {
#pragma unroll
        for (int half = 0; half < 2; half++) {
            const int t = wm + (lane >> 2) + half * 8;
            const int p = wp + nt * 8 + (lane & 3) * 2;
            const float e = expf(s_ca[t]);
            float2 xv = *(const float2*)(xsrc + (size_t)t * CONVDIM + p);
            float2 yo = *(float2*)(yout + (size_t)t * DINNER + p);
            yo.x += e * acc[nt][half * 2 + 0] + Dh * xv.x;
            yo.y += e * acc[nt][half * 2 + 1] + Dh * xv.y;
            *(float2*)(yout + (size_t)t * DINNER + p) = yo;
        }
    }
}

// ============== gate + RMSnorm (tf32-rounded out) ==============
__global__ __launch_bounds__(256) void gatenorm_kernel(const float* __restrict__ norm_w)
{
    const int row = blockIdx.x;
    const float* zrow = g_zx + (size_t)row * DIP;
    float* yrow = g_y + (size_t)row * DINNER;

    float v[8];
    float ss = 0.f;
#pragma unroll
    for (int i = 0; i < 8; i++) {
        const int c = threadIdx.x + i * 256;
        float d = yrow[c];
        float z = zrow[c];
        float g = d * (z / (1.f + expf(-z)));
        v[i] = g;
        ss = fmaf(g, g, ss);
    }
#pragma unroll
    for (int o = 16; o; o >>= 1) ss += __shfl_xor_sync(0xffffffffu, ss, o);

    __shared__ float red[8];
    if ((threadIdx.x & 31) == 0) red[threadIdx.x >> 5] = ss;
    __syncthreads();
    float tot = 0.f;
#pragma unroll
    for (int w = 0; w < 8; w++) tot += red[w];
    const float scale = rsqrtf(tot * (1.f / (float)DINNER) + 1e-5f);

#pragma unroll
    for (int i = 0; i < 8; i++) {
        const int c = threadIdx.x + i * 256;
        yrow[c] = __uint_as_float(f2tf(v[i] * scale * norm_w[c]));
    }
}

// ============== launch ==============
extern "C" void kernel_launch(void* const* d_in, const int* in_sizes, int n_in,
                              void* d_out, int out_size)
{
    const float* x          = (const float*)d_in[0];
    const float* in_proj_w  = (const float*)d_in[1];
    const float* conv_w     = (const float*)d_in[2];
    const float* conv_b     = (const float*)d_in[3];
    const float* dt_bias    = (const float*)d_in[4];
    const float* A_log      = (const float*)d_in[5];
    const float* Dp         = (const float*)d_in[6];
    const float* norm_w     = (const float*)d_in[7];
    const float* out_proj_w = (const float*)d_in[8];
    float* out = (float*)d_out;

    float *zx, *yb, *xc, *w1, *w2;
    cudaGetSymbolAddress((void**)&zx, g_zx);
    cudaGetSymbolAddress((void**)&yb, g_y);
    cudaGetSymbolAddress((void**)&xc, g_xc);
    cudaGetSymbolAddress((void**)&w1, g_w1);
    cudaGetSymbolAddress((void**)&w2, g_w2);

    const int gemm_smem = 3 * TSTAGE_B;
    const int g_smem  = (4 * Q * BSTR) * 4;
    const int k1_smem = (2 * Q * BSTR + 4 * 64 * XSTR + 2 * Q * XSTR + 3 * Q) * 4;
    const int k3_smem = (2 * Q * BSTR + 64 * BSTR + Q) * 4;
    cudaFuncSetAttribute(gemm_tf32_ca_kernel,
                         cudaFuncAttributeMaxDynamicSharedMemorySize, gemm_smem);
    cudaFuncSetAttribute(ssd_g_kernel,
                         cudaFuncAttributeMaxDynamicSharedMemorySize, g_smem);
    cudaFuncSetAttribute(ssd_chunk_kernel,
                         cudaFuncAttributeMaxDynamicSharedMemorySize, k1_smem);
    cudaFuncSetAttribute(ssd_inter_kernel,
                         cudaFuncAttributeMaxDynamicSharedMemorySize, k3_smem);

    {
        int n4;
        n4 = (BL * DMODEL) / 4;
        cvt_tf32_kernel<<<(n4 + 255) / 256, 256>>>(x, xc, n4);
        n4 = (DIP * DMODEL) / 4;
        cvt_tf32_kernel<<<(n4 + 255) / 256, 256>>>(in_proj_w, w1, n4);
        n4 = (DOUT * DINNER) / 4;
        cvt_tf32_kernel<<<(n4 + 255) / 256, 256>>>(out_proj_w, w2, n4);
    }
    {
        dim3 grid((DIP + 127) / 128, BL / 128);
        gemm_tf32_ca_kernel<<<grid, 256, gemm_smem>>>(xc, w1, zx, BL, DIP, DMODEL);
    }
    {
        const int total = BL * (CONVDIM / 4);
        conv_silu_kernel<<<(total + 255) / 256, 256>>>(conv_w, conv_b);
    }
    dt_kernel<<<(BL * NHEADS) / 256, 256>>>(dt_bias, A_log);
    ssd_g_kernel<<<Bb * NC, 256, g_smem>>>();
    ssd_chunk_kernel<<<Bb * NC * NHEADS, 256, k1_smem>>>();
    ssd_state_scan_kernel<<<Bb * NHEADS * 8, 256>>>();
    ssd_inter_kernel<<<Bb * NC * NHEADS, 256, k3_smem>>>(Dp);
    gatenorm_kernel<<<BL, 256>>>(norm_w);
    {
        dim3 grid(DOUT / 128, BL / 128);
        gemm_tf32_ca_kernel<<<grid, 256, gemm_smem>>>(yb, w2, out, BL, DOUT, DINNER);
    }
}